// round 16
// baseline (speedup 1.0000x reference)
#include <cuda_runtime.h>
#include <cuda_fp16.h>
#include <cstdint>

// Problem constants
#define NN   8192
#define DD   512
#define NCLS 10
#define REG_E 0.05f
#define NIT  20
#define SHIFT 15.0f          // exp2 shift for P storage
#define SHIFT_MUL 32768.0f   // 2^15

static constexpr size_t NN2 = (size_t)NN * (size_t)NN;

// ---------------- scratch (device globals; no allocation) ----------------
static __device__ __half g_Ch[NN2];           // 128 MiB: CX (fp16)
static __device__ unsigned char g_Pa[NN2];     // 64 MiB: P' hi byte (s|e5|m2)
static __device__ unsigned char g_Pb[NN2 / 2]; // 32 MiB: P' mantissa nibbles (m3..m6), 2/byte
static __device__ __half g_Ah[NN * DD];       // XP fp16
static __device__ __half g_Bh[NN * DD];       // XQ fp16
static __device__ float g_xp2[NN], g_xq2[NN], g_yp2[NN], g_yq2[NN];
static __device__ float g_z[NN], g_w[NN];
static __device__ float g_part[256 * NN];     // column partials (8 MB)
static __device__ float g_bpart[512];         // final reduction partials
static __device__ unsigned g_max_cx, g_max_cy, g_max_c;

// ---------------- generic helpers ----------------
__device__ __forceinline__ float blockReduceSum(float v) {
    __shared__ float red[32];
    unsigned lane = threadIdx.x & 31u, wid = threadIdx.x >> 5;
#pragma unroll
    for (int o = 16; o > 0; o >>= 1) v += __shfl_down_sync(0xffffffffu, v, o);
    if (lane == 0) red[wid] = v;
    __syncthreads();
    int nw = (blockDim.x + 31) >> 5;
    v = (threadIdx.x < (unsigned)nw) ? red[threadIdx.x] : 0.f;
    if (wid == 0) {
#pragma unroll
        for (int o = 16; o > 0; o >>= 1) v += __shfl_down_sync(0xffffffffu, v, o);
    }
    return v;  // valid in thread 0
}

__device__ __forceinline__ double blockReduceSumD(double v) {
    __shared__ double redd[32];
    unsigned lane = threadIdx.x & 31u, wid = threadIdx.x >> 5;
#pragma unroll
    for (int o = 16; o > 0; o >>= 1) v += __shfl_down_sync(0xffffffffu, v, o);
    if (lane == 0) redd[wid] = v;
    __syncthreads();
    int nw = (blockDim.x + 31) >> 5;
    v = (threadIdx.x < (unsigned)nw) ? redd[threadIdx.x] : 0.0;
    if (wid == 0) {
#pragma unroll
        for (int o = 16; o > 0; o >>= 1) v += __shfl_down_sync(0xffffffffu, v, o);
    }
    return v;
}

// fast exp2 for y in [-30, 16]; FMA-only (no MUFU). rel err ~1e-7.
__device__ __forceinline__ float fexp2(float y) {
    float fk = y + 12582912.0f;
    int   k  = __float_as_int(fk) - 0x4B400000;
    float r  = y - (fk - 12582912.0f);
    float p  = 1.5403530e-4f;
    p = fmaf(p, r, 1.3333558e-3f);
    p = fmaf(p, r, 9.6181291e-3f);
    p = fmaf(p, r, 5.5504109e-2f);
    p = fmaf(p, r, 2.4022651e-1f);
    p = fmaf(p, r, 6.9314718e-1f);
    p = fmaf(p, r, 1.0f);
    return p * __int_as_float((k + 127) << 23);
}

// ---------------- mma / cp.async helpers (sm_80+ PTX, works on plain sm_100) ----
__device__ __forceinline__ void mma_f16(float* d, const uint32_t* a, const uint32_t* b) {
    asm volatile(
        "mma.sync.aligned.m16n8k16.row.col.f32.f16.f16.f32 "
        "{%0,%1,%2,%3}, {%4,%5,%6,%7}, {%8,%9}, {%0,%1,%2,%3};"
        : "+f"(d[0]), "+f"(d[1]), "+f"(d[2]), "+f"(d[3])
        : "r"(a[0]), "r"(a[1]), "r"(a[2]), "r"(a[3]), "r"(b[0]), "r"(b[1]));
}
__device__ __forceinline__ uint32_t smem_u32(const void* p) {
    uint32_t a;
    asm("{ .reg .u64 t; cvta.to.shared.u64 t, %1; cvt.u32.u64 %0, t; }" : "=r"(a) : "l"(p));
    return a;
}
#define CP_ASYNC16(dst, src) \
    asm volatile("cp.async.cg.shared.global [%0], [%1], 16;" :: "r"(dst), "l"(src) : "memory")
#define CP_COMMIT() asm volatile("cp.async.commit_group;" ::: "memory")
#define CP_WAIT0()  asm volatile("cp.async.wait_group 0;" ::: "memory")

// fp16 C decode: 4 cols from a uint2
__device__ __forceinline__ void dec_c4(uint2 cu, float* c) {
    float2 a = __half22float2(*reinterpret_cast<__half2*>(&cu.x));
    float2 b = __half22float2(*reinterpret_cast<__half2*>(&cu.y));
    c[0] = a.x; c[1] = a.y; c[2] = b.x; c[3] = b.y;
}
// 12-bit P decode: 8 cols from hi-byte uint2 + nibble uint32
__device__ __forceinline__ void dec8_12(uint2 hb, uint32_t nb, float* f) {
    uint32_t h0 = __byte_perm(hb.x, 0, 0x1404) | ((nb & 0x0000000Fu) << 4)  | ((nb & 0x000000F0u) << 16);
    uint32_t h1 = __byte_perm(hb.x, 0, 0x3424) | ((nb & 0x00000F00u) >> 4)  | ((nb & 0x0000F000u) << 8);
    uint32_t h2 = __byte_perm(hb.y, 0, 0x1404) | ((nb & 0x000F0000u) >> 12) | ((nb & 0x00F00000u));
    uint32_t h3 = __byte_perm(hb.y, 0, 0x3424) | ((nb & 0x0F000000u) >> 20) | ((nb & 0xF0000000u) >> 8);
    float2 a = __half22float2(*reinterpret_cast<__half2*>(&h0));
    float2 b = __half22float2(*reinterpret_cast<__half2*>(&h1));
    float2 c = __half22float2(*reinterpret_cast<__half2*>(&h2));
    float2 d = __half22float2(*reinterpret_cast<__half2*>(&h3));
    f[0] = a.x; f[1] = a.y; f[2] = b.x; f[3] = b.y;
    f[4] = c.x; f[5] = c.y; f[6] = d.x; f[7] = d.y;
}

// ---------------- small kernels ----------------
// init + Y-norms (keeps gemm at launch slot #4 for ncu)
__global__ void k_init(const float* __restrict__ YP, const float* __restrict__ YQ) {
    int t = blockIdx.x * blockDim.x + threadIdx.x;
    if (t == 0) { g_max_cx = 0u; g_max_cy = 0u; g_max_c = 0u; }
    if (t < NN) {
        g_w[t] = 1.0f;
        float sp = 0.f, sq = 0.f;
#pragma unroll
        for (int c = 0; c < NCLS; c++) {
            float tp = YP[(size_t)t * NCLS + c];
            float tq = YQ[(size_t)t * NCLS + c];
            sp += tp * tp; sq += tq * tq;
        }
        g_yp2[t] = sp; g_yq2[t] = sq;
    }
}

__global__ void k_norm512(const float* __restrict__ XP, const float* __restrict__ XQ) {
    int i = blockIdx.x;
    const float* X = blockIdx.y ? XQ : XP;
    float4 v = reinterpret_cast<const float4*>(X)[(size_t)i * (DD / 4) + threadIdx.x];
    float s = v.x * v.x + v.y * v.y + v.z * v.z + v.w * v.w;
    s = blockReduceSum(s);
    if (threadIdx.x == 0) (blockIdx.y ? g_xq2 : g_xp2)[i] = s;
}

// convert X to fp16 planes (rn)
__global__ void __launch_bounds__(256) k_split(const float* __restrict__ XP, const float* __restrict__ XQ) {
    const float4* src = reinterpret_cast<const float4*>(blockIdx.y ? XQ : XP);
    __half* Hh = blockIdx.y ? g_Bh : g_Ah;
    int n4 = NN * DD / 4;
    for (int i = blockIdx.x * 256 + threadIdx.x; i < n4; i += gridDim.x * 256) {
        float4 v = src[i];
        union { __half2 h[2]; uint2 u; } ph;
        ph.h[0] = __floats2half2_rn(v.x, v.y);
        ph.h[1] = __floats2half2_rn(v.z, v.w);
        reinterpret_cast<uint2*>(Hh)[i] = ph.u;
    }
}

// ---------------- single-pass FP16 mma.sync GEMM: CX tile + maxCX/maxCY ----------
#define ROWW 20                           // words per row (32 halves + pad)
#define PLANE_B (128 * ROWW * 4)          // bytes per plane: 10240
#define BUF_B (2 * PLANE_B)               // planes Ah, Bh: 20480
#define SMEM_GEMM (2 * BUF_B)             // 40960

__global__ void __launch_bounds__(256, 2)
k_gemm_mma(const float* __restrict__ YPg, const float* __restrict__ YQg) {
    extern __shared__ float sm[];
    const int tid = threadIdx.x;
    const int wid = tid >> 5, lane = tid & 31;
    const int warp_m = wid >> 2, warp_n = wid & 3;
    const int g = lane >> 2, t4 = lane & 3;
    const int row0 = blockIdx.y * 128;
    const int col0 = blockIdx.x * 128;

    const uint32_t smb = smem_u32(sm);

    float acc[4][4][4];
#pragma unroll
    for (int mt = 0; mt < 4; mt++)
#pragma unroll
        for (int nt = 0; nt < 4; nt++)
#pragma unroll
            for (int q = 0; q < 4; q++) acc[mt][nt][q] = 0.f;

    auto issue = [&](int ch, int buf) {
        const uint32_t base = smb + (uint32_t)buf * BUF_B;
#pragma unroll
        for (int q = 0; q < 4; q++) {
            int idx = tid + q * 256;          // 0..1023
            int plane = idx >> 9;             // 0=Ah,1=Bh
            int r = (idx >> 2) & 127;
            int c16 = idx & 3;
            uint32_t dst = base + (uint32_t)plane * PLANE_B + (uint32_t)(r * 80 + c16 * 16);
            const __half* gp = plane ? g_Bh : g_Ah;
            int rg = (plane ? col0 : row0) + r;
            const __half* src = gp + (size_t)rg * DD + ch * 32 + c16 * 8;
            CP_ASYNC16(dst, src);
        }
        CP_COMMIT();
    };

    issue(0, 0);
    for (int ch = 0; ch < 16; ch++) {
        const int buf = ch & 1;
        CP_WAIT0();
        __syncthreads();
        if (ch < 15) issue(ch + 1, buf ^ 1);
        const uint32_t* Ah = reinterpret_cast<const uint32_t*>(sm) + buf * (BUF_B / 4);
        const uint32_t* Bh = Ah + PLANE_B / 4;
#pragma unroll
        for (int kk = 0; kk < 2; kk++) {
            const int kbw = kk * 8;
            uint32_t ah[4][4];
#pragma unroll
            for (int mt = 0; mt < 4; mt++) {
                int base = (warp_m * 64 + mt * 16 + g) * ROWW + kbw + t4;
                ah[mt][0] = Ah[base];       ah[mt][1] = Ah[base + 8 * ROWW];
                ah[mt][2] = Ah[base + 4];   ah[mt][3] = Ah[base + 8 * ROWW + 4];
            }
            uint32_t bh[4][2];
#pragma unroll
            for (int nt = 0; nt < 4; nt++) {
                int base = (warp_n * 32 + nt * 8 + g) * ROWW + kbw + t4;
                bh[nt][0] = Bh[base];  bh[nt][1] = Bh[base + 4];
            }
#pragma unroll
            for (int mt = 0; mt < 4; mt++)
#pragma unroll
                for (int nt = 0; nt < 4; nt++)
                    mma_f16(acc[mt][nt], ah[mt], bh[nt]);
        }
        __syncthreads();
    }

    // ---- epilogue staging (reuse smem) ----
    if (tid < 128) {
        sm[tid]        = g_xq2[col0 + tid];
        sm[128 + tid]  = g_yq2[col0 + tid];
        sm[2816 + tid] = g_yp2[row0 + tid];
    }
    for (int i = tid; i < 128 * NCLS; i += 256) {
        sm[256 + i]  = YQg[(size_t)col0 * NCLS + i];
        sm[1536 + i] = YPg[(size_t)row0 * NCLS + i];
    }
    __syncthreads();

    float maxcx = 0.f;
#pragma unroll
    for (int mt = 0; mt < 4; mt++) {
        const int r1 = warp_m * 64 + mt * 16 + g;
        const int r2 = r1 + 8;
        const float xp2a = g_xp2[row0 + r1];
        const float xp2b = g_xp2[row0 + r2];
#pragma unroll
        for (int nt = 0; nt < 4; nt++) {
            const int n0 = warp_n * 32 + nt * 8 + 2 * t4;
            const float xq0 = sm[n0], xq1 = sm[n0 + 1];
            float c00 = fmaxf(xp2a + xq0 - 2.f * acc[mt][nt][0], 0.f);
            float c01 = fmaxf(xp2a + xq1 - 2.f * acc[mt][nt][1], 0.f);
            float c10 = fmaxf(xp2b + xq0 - 2.f * acc[mt][nt][2], 0.f);
            float c11 = fmaxf(xp2b + xq1 - 2.f * acc[mt][nt][3], 0.f);
            __half2 h0 = __floats2half2_rn(c00, c01);
            __half2 h1 = __floats2half2_rn(c10, c11);
            *reinterpret_cast<__half2*>(&g_Ch[(size_t)(row0 + r1) * NN + col0 + n0]) = h0;
            *reinterpret_cast<__half2*>(&g_Ch[(size_t)(row0 + r2) * NN + col0 + n0]) = h1;
            float2 q0 = __half22float2(h0);
            float2 q1 = __half22float2(h1);
            maxcx = fmaxf(maxcx, fmaxf(fmaxf(q0.x, q0.y), fmaxf(q1.x, q1.y)));
        }
    }
#pragma unroll
    for (int o = 16; o > 0; o >>= 1) maxcx = fmaxf(maxcx, __shfl_xor_sync(0xffffffffu, maxcx, o));
    if (lane == 0) atomicMax(&g_max_cx, __float_as_uint(maxcx));

    {
        const int r = tid & 127;
        const int j0 = (tid >> 7) * 64;
        float ypv[NCLS];
#pragma unroll
        for (int d = 0; d < NCLS; d++) ypv[d] = sm[1536 + r * NCLS + d];
        const float yp2r = sm[2816 + r];
        float mx = 0.f;
        for (int j = j0; j < j0 + 64; j++) {
            float dot = 0.f;
#pragma unroll
            for (int d = 0; d < NCLS; d++) dot = fmaf(ypv[d], sm[256 + j * NCLS + d], dot);
            float cy = fmaxf(yp2r + sm[128 + j] - 2.f * dot, 0.f);
            mx = fmaxf(mx, cy);
        }
#pragma unroll
        for (int o = 16; o > 0; o >>= 1) mx = fmaxf(mx, __shfl_xor_sync(0xffffffffu, mx, o));
        if (lane == 0) atomicMax(&g_max_cy, __float_as_uint(mx));
    }
}

// ---------------- max(C) over all elements (C = CX + lw*CY on the fly) ----------------
__global__ void __launch_bounds__(256) k_maxc(const float* __restrict__ YP, const float* __restrict__ YQ) {
    __shared__ float YPs[16][NCLS];
    __shared__ float yp2s[16];
    const int i0 = blockIdx.x * 16;
    const int tid = threadIdx.x;
    if (tid < 16 * NCLS) { int r = tid / NCLS, c = tid - r * NCLS; YPs[r][c] = YP[(size_t)(i0 + r) * NCLS + c]; }
    if (tid < 16) yp2s[tid] = g_yp2[i0 + tid];
    __syncthreads();
    float cxm = __uint_as_float(g_max_cx);
    float cym = __uint_as_float(g_max_cy);
    float lw = (cym == 0.f) ? 0.f : cxm / cym;
    float localmax = 0.f;
    for (int j0 = tid * 4; j0 < NN; j0 += 1024) {
        float yq[4][NCLS], yq2[4];
#pragma unroll
        for (int c = 0; c < 4; c++) {
#pragma unroll
            for (int d = 0; d < NCLS; d += 2) {
                float2 t = __ldg(reinterpret_cast<const float2*>(&YQ[(size_t)(j0 + c) * NCLS + d]));
                yq[c][d] = t.x; yq[c][d + 1] = t.y;
            }
            yq2[c] = g_yq2[j0 + c];
        }
#pragma unroll
        for (int r = 0; r < 16; r++) {
            uint2 cu = *reinterpret_cast<const uint2*>(&g_Ch[(size_t)(i0 + r) * NN + j0]);
            float cxa[4]; dec_c4(cu, cxa);
#pragma unroll
            for (int c = 0; c < 4; c++) {
                float dot = 0.f;
#pragma unroll
                for (int d = 0; d < NCLS; d++) dot = fmaf(YPs[r][d], yq[c][d], dot);
                float cy = fmaxf(yp2s[r] + yq2[c] - 2.f * dot, 0.f);
                localmax = fmaxf(localmax, cxa[c] + lw * cy);
            }
        }
    }
#pragma unroll
    for (int o = 16; o > 0; o >>= 1)
        localmax = fmaxf(localmax, __shfl_xor_sync(0xffffffffu, localmax, o));
    if ((tid & 31) == 0) atomicMax(&g_max_c, __float_as_uint(localmax));
}

// ---------------- P' = 2^SHIFT * exp(-C/(reg*cmax)) as 12-bit (hi byte + nibble) ----
__global__ void __launch_bounds__(256) k_exp(const float* __restrict__ YP, const float* __restrict__ YQ) {
    __shared__ float YPs[16][NCLS];
    __shared__ float yp2s[16];
    const int i0 = blockIdx.x * 16;
    const int tid = threadIdx.x;
    if (tid < 16 * NCLS) { int r = tid / NCLS, c = tid - r * NCLS; YPs[r][c] = YP[(size_t)(i0 + r) * NCLS + c]; }
    if (tid < 16) yp2s[tid] = g_yp2[i0 + tid];
    __syncthreads();
    float cxm = __uint_as_float(g_max_cx);
    float cym = __uint_as_float(g_max_cy);
    float lw = (cym == 0.f) ? 0.f : cxm / cym;
    float cmax = __uint_as_float(g_max_c);
    float sc = 1.4426950408889634f / (REG_E * cmax);
    for (int j0 = tid * 4; j0 < NN; j0 += 1024) {
        float yq[4][NCLS], yq2[4];
#pragma unroll
        for (int c = 0; c < 4; c++) {
#pragma unroll
            for (int d = 0; d < NCLS; d += 2) {
                float2 t = __ldg(reinterpret_cast<const float2*>(&YQ[(size_t)(j0 + c) * NCLS + d]));
                yq[c][d] = t.x; yq[c][d + 1] = t.y;
            }
            yq2[c] = g_yq2[j0 + c];
        }
#pragma unroll
        for (int r = 0; r < 16; r++) {
            uint2 cu = *reinterpret_cast<const uint2*>(&g_Ch[(size_t)(i0 + r) * NN + j0]);
            float cxa[4]; dec_c4(cu, cxa);
            uint32_t hr[4];
#pragma unroll
            for (int c = 0; c < 4; c++) {
                float dot = 0.f;
#pragma unroll
                for (int d = 0; d < NCLS; d++) dot = fmaf(YPs[r][d], yq[c][d], dot);
                float cy = fmaxf(yp2s[r] + yq2[c] - 2.f * dot, 0.f);
                float v = cxa[c] + lw * cy;
                float pv = fexp2(fmaf(-v, sc, SHIFT));
                // round to 12-bit grid (add half-ulp of 12-bit = 8; carries propagate correctly)
                hr[c] = (uint32_t)__half_as_ushort(__float2half_rn(pv)) + 8u;
            }
            uint32_t hib = (hr[0] >> 8) | ((hr[1] >> 8) << 8) | ((hr[2] >> 8) << 16) | ((hr[3] >> 8) << 24);
            uint32_t nib = ((hr[0] >> 4) & 0xFu) | (((hr[1] >> 4) & 0xFu) << 4)
                         | (((hr[2] >> 4) & 0xFu) << 8) | (((hr[3] >> 4) & 0xFu) << 12);
            size_t base = (size_t)(i0 + r) * NN + j0;
            *reinterpret_cast<uint32_t*>(&g_Pa[base]) = hib;
            *reinterpret_cast<uint16_t*>(&g_Pb[base >> 1]) = (uint16_t)nib;
        }
    }
}

// ---------------- fused Sinkhorn iteration: one pass over 12-bit P ----------------
// Grid 256 x 512, 2 blocks/SM. Block owns 32 rows, 16 strips of 2 rows.
// Strip staged in SMEM (cp.async, double-buffered): Pa 2x16KB + Pb 2x8KB.
#define IT_ROWS 32
#define STRIP 2
#define NSTRIP 16
#define PA_STRIP_B 16384                  // 2 rows x 8192 hi-bytes
#define PB_STRIP_B 8192                   // 2 rows x 4096 nibble-bytes
#define SMEM_IT (2 * PA_STRIP_B + 2 * PB_STRIP_B + 512)   // 49664

__global__ void __launch_bounds__(512, 2) k_iter() {
    extern __shared__ char smc[];
    float* zsm = reinterpret_cast<float*>(smc + 2 * PA_STRIP_B + 2 * PB_STRIP_B);  // [2]
    float* red = zsm + 4;                                                          // [32]
    const int tid = threadIdx.x;
    const int wid = tid >> 5, lane = tid & 31;
    const int r0 = blockIdx.x * IT_ROWS;
    const uint32_t smb = smem_u32(smc);
    const uint32_t pb_off = 2 * PA_STRIP_B;

    float wreg[2][8];
#pragma unroll
    for (int k = 0; k < 2; k++) {
        const float* wp = &g_w[(k * 512 + tid) * 8];
        float4 a = *reinterpret_cast<const float4*>(wp);
        float4 b = *reinterpret_cast<const float4*>(wp + 4);
        wreg[k][0] = a.x; wreg[k][1] = a.y; wreg[k][2] = a.z; wreg[k][3] = a.w;
        wreg[k][4] = b.x; wreg[k][5] = b.y; wreg[k][6] = b.z; wreg[k][7] = b.w;
    }
    float colacc[2][8];
#pragma unroll
    for (int k = 0; k < 2; k++)
#pragma unroll
        for (int i = 0; i < 8; i++) colacc[k][i] = 0.f;

    auto issue = [&](int s, int b) {
        const unsigned char* basea = g_Pa + (size_t)(r0 + s * STRIP) * NN;
        const unsigned char* baseb = g_Pb + (size_t)(r0 + s * STRIP) * (NN / 2);
        // Pa: 1024 chunks of 16B (512 per row)
#pragma unroll
        for (int q = 0; q < 2; q++) {
            int idx = tid + q * 512;                 // 0..1023
            int rr = idx >> 9, cb = idx & 511;
            uint32_t dst = smb + (uint32_t)b * PA_STRIP_B + (uint32_t)idx * 16;
            CP_ASYNC16(dst, basea + (size_t)rr * NN + cb * 16);
        }
        // Pb: 512 chunks of 16B (256 per row)
        {
            int idx = tid;                            // 0..511
            int rr = idx >> 8, cb = idx & 255;
            uint32_t dst = smb + pb_off + (uint32_t)b * PB_STRIP_B + (uint32_t)idx * 16;
            CP_ASYNC16(dst, baseb + (size_t)rr * (NN / 2) + cb * 16);
        }
        CP_COMMIT();
    };

    issue(0, 0);
    for (int s = 0; s < NSTRIP; s++) {
        const int b = s & 1;
        CP_WAIT0();
        __syncthreads();
        if (s < NSTRIP - 1) issue(s + 1, b ^ 1);
        const uint2* Pa = reinterpret_cast<const uint2*>(smc + b * PA_STRIP_B);           // [r*1024 + c8]
        const uint32_t* Pb = reinterpret_cast<const uint32_t*>(smc + pb_off + b * PB_STRIP_B); // [r*1024 + c8]

        // pass 1: row sums
        float rp[STRIP] = {0.f, 0.f};
#pragma unroll
        for (int r = 0; r < STRIP; r++)
#pragma unroll
            for (int k = 0; k < 2; k++) {
                int c8 = k * 512 + tid;
                float f[8]; dec8_12(Pa[r * 1024 + c8], Pb[r * 1024 + c8], f);
                float s0 = fmaf(f[0], wreg[k][0], f[1] * wreg[k][1]);
                s0 = fmaf(f[2], wreg[k][2], s0); s0 = fmaf(f[3], wreg[k][3], s0);
                float s1 = fmaf(f[4], wreg[k][4], f[5] * wreg[k][5]);
                s1 = fmaf(f[6], wreg[k][6], s1); s1 = fmaf(f[7], wreg[k][7], s1);
                rp[r] += s0 + s1;
            }
#pragma unroll
        for (int r = 0; r < STRIP; r++) {
            float v = rp[r];
#pragma unroll
            for (int o = 16; o > 0; o >>= 1) v += __shfl_down_sync(0xffffffffu, v, o);
            if (lane == 0) red[r * 16 + wid] = v;
        }
        __syncthreads();
        if (tid < STRIP) {
            float sum = 0.f;
#pragma unroll
            for (int w2 = 0; w2 < 16; w2++) sum += red[tid * 16 + w2];
            float z = (1.0f / NN) / sum;
            zsm[tid] = z;
            g_z[r0 + s * STRIP + tid] = z;
        }
        __syncthreads();

        // pass 2: column partials
#pragma unroll
        for (int r = 0; r < STRIP; r++) {
            float zz = zsm[r];
#pragma unroll
            for (int k = 0; k < 2; k++) {
                int c8 = k * 512 + tid;
                float f[8]; dec8_12(Pa[r * 1024 + c8], Pb[r * 1024 + c8], f);
#pragma unroll
                for (int i = 0; i < 8; i++) colacc[k][i] = fmaf(f[i], zz, colacc[k][i]);
            }
        }
    }

#pragma unroll
    for (int k = 0; k < 2; k++) {
        float* dst = &g_part[(size_t)blockIdx.x * NN + (size_t)(k * 512 + tid) * 8];
        *reinterpret_cast<float4*>(dst)     = make_float4(colacc[k][0], colacc[k][1], colacc[k][2], colacc[k][3]);
        *reinterpret_cast<float4*>(dst + 4) = make_float4(colacc[k][4], colacc[k][5], colacc[k][6], colacc[k][7]);
    }
}

// w = (1/M) / colsum over 256 block partials -- parallel + deterministic.
__global__ void __launch_bounds__(256) k_colred() {
    __shared__ float red2[8][32];
    const int tid = threadIdx.x;
    const int g = tid >> 5, jl = tid & 31;
    const int j = blockIdx.x * 32 + jl;
    float s = 0.f;
#pragma unroll 8
    for (int ch = g * 32; ch < g * 32 + 32; ch++)
        s += g_part[(size_t)ch * NN + j];
    red2[g][jl] = s;
    __syncthreads();
    if (tid < 32) {
        float t = 0.f;
#pragma unroll
        for (int q = 0; q < 8; q++) t += red2[q][tid];
        g_w[blockIdx.x * 32 + tid] = (1.0f / NN) / t;
    }
}

// ---------------- final objective ----------------
__global__ void __launch_bounds__(256) k_final(const float* __restrict__ YP, const float* __restrict__ YQ) {
    __shared__ float YPs[16][NCLS];
    __shared__ float yp2s[16];
    __shared__ float zs[16];
    const int i0 = blockIdx.x * 16;
    const int tid = threadIdx.x;
    if (tid < 16 * NCLS) { int r = tid / NCLS, c = tid - r * NCLS; YPs[r][c] = YP[(size_t)(i0 + r) * NCLS + c]; }
    if (tid < 16) { yp2s[tid] = g_yp2[i0 + tid]; zs[tid] = g_z[i0 + tid] * SHIFT_MUL; }
    __syncthreads();
    float cxm = __uint_as_float(g_max_cx);
    float cym = __uint_as_float(g_max_cy);
    float lw = (cym == 0.f) ? 0.f : cxm / cym;
    float cmax = __uint_as_float(g_max_c);
    float sc = 1.4426950408889634f / (REG_E * cmax);
    float acc = 0.f;
    for (int j0 = tid * 4; j0 < NN; j0 += 1024) {
        float yq[4][NCLS], yq2[4];
#pragma unroll
        for (int c = 0; c < 4; c++) {
#pragma unroll
            for (int d = 0; d < NCLS; d += 2) {
                float2 t = __ldg(reinterpret_cast<const float2*>(&YQ[(size_t)(j0 + c) * NCLS + d]));
                yq[c][d] = t.x; yq[c][d + 1] = t.y;
            }
            yq2[c] = g_yq2[j0 + c];
        }
        float4 wv = *reinterpret_cast<const float4*>(&g_w[j0]);
        float wa[4] = {wv.x, wv.y, wv.z, wv.w};
#pragma unroll
        for (int r = 0; r < 16; r++) {
            uint2 cu = *reinterpret_cast<const uint2*>(&g_Ch[(size_t)(i0 + r) * NN + j0]);
            float cxa[4]; dec_c4(cu, cxa);
            float zi = zs[r];
#pragma unroll
            for (int c = 0; c < 4; c++) {
                float dot = 0.f;
#pragma unroll
                for (int d = 0; d < NCLS; d++) dot = fmaf(YPs[r][d], yq[c][d], dot);
                float cy = fmaxf(yp2s[r] + yq2[c] - 2.f * dot, 0.f);
                float v = cxa[c] + lw * cy;
                float p = fexp2(-v * sc);
                acc = fmaf(v * p, zi * wa[c], acc);
            }
        }
    }
    acc = blockReduceSum(acc);
    if (tid == 0) g_bpart[blockIdx.x] = acc;
}

__global__ void __launch_bounds__(256) k_finalred(float* out) {
    double s = 0.0;
    for (int t = threadIdx.x; t < 512; t += 256) s += (double)g_bpart[t];
    s = blockReduceSumD(s);
    if (threadIdx.x == 0) out[0] = (float)s;
}

// ---------------- launch ----------------
extern "C" void kernel_launch(void* const* d_in, const int* in_sizes, int n_in,
                              void* d_out, int out_size) {
    const float* XQ = (const float*)d_in[0];   // (8192, 512)
    const float* YQ = (const float*)d_in[1];   // (8192, 10)
    const float* XP = (const float*)d_in[2];   // (8192, 512)
    const float* YP = (const float*)d_in[3];   // (8192, 10)
    float* out = (float*)d_out;

    cudaFuncSetAttribute(k_gemm_mma, cudaFuncAttributeMaxDynamicSharedMemorySize, SMEM_GEMM);
    cudaFuncSetAttribute(k_iter, cudaFuncAttributeMaxDynamicSharedMemorySize, SMEM_IT);

    k_init<<<32, 256>>>(YP, YQ);
    k_norm512<<<dim3(NN, 2), 128>>>(XP, XQ);
    k_split<<<dim3(512, 2), 256>>>(XP, XQ);

    k_gemm_mma<<<dim3(64, 64), 256, SMEM_GEMM>>>(YP, YQ);   // launch #4: ncu target
    k_maxc<<<NN / 16, 256>>>(YP, YQ);
    k_exp<<<NN / 16, 256>>>(YP, YQ);

    for (int it = 0; it < NIT; it++) {
        k_iter<<<256, 512, SMEM_IT>>>();
        k_colred<<<256, 256>>>();
    }

    k_final<<<NN / 16, 256>>>(YP, YQ);
    k_finalred<<<1, 256>>>(out);
}

// round 17
// speedup vs baseline: 1.1684x; 1.1684x over previous
#include <cuda_runtime.h>
#include <cuda_fp16.h>
#include <cstdint>

// Problem constants
#define NN   8192
#define DD   512
#define NCLS 10
#define REG_E 0.05f
#define NIT  20
#define SHIFT 15.0f          // exp2 shift for fp16 P storage
#define SHIFT_MUL 32768.0f   // 2^15

static constexpr size_t NN2 = (size_t)NN * (size_t)NN;

// ---------------- scratch (device globals; no allocation) ----------------
static __device__ __half g_Ch[NN2];           // 128 MiB: CX (fp16)
static __device__ __half g_Ph[NN2];           // 128 MiB: P' = 2^15 * exp(-C/(reg*cmax))
static __device__ __half g_Ah[NN * DD];       // XP fp16
static __device__ __half g_Bh[NN * DD];       // XQ fp16
static __device__ float g_xp2[NN], g_xq2[NN], g_yp2[NN], g_yq2[NN];
static __device__ float g_z[NN], g_w[NN];
static __device__ float g_part[256 * NN];     // column partials (8 MB)
static __device__ float g_bpart[512];         // final reduction partials
static __device__ unsigned g_max_cx, g_max_cy, g_max_c;

// ---------------- generic helpers ----------------
__device__ __forceinline__ float blockReduceSum(float v) {
    __shared__ float red[32];
    unsigned lane = threadIdx.x & 31u, wid = threadIdx.x >> 5;
#pragma unroll
    for (int o = 16; o > 0; o >>= 1) v += __shfl_down_sync(0xffffffffu, v, o);
    if (lane == 0) red[wid] = v;
    __syncthreads();
    int nw = (blockDim.x + 31) >> 5;
    v = (threadIdx.x < (unsigned)nw) ? red[threadIdx.x] : 0.f;
    if (wid == 0) {
#pragma unroll
        for (int o = 16; o > 0; o >>= 1) v += __shfl_down_sync(0xffffffffu, v, o);
    }
    return v;  // valid in thread 0
}

__device__ __forceinline__ double blockReduceSumD(double v) {
    __shared__ double redd[32];
    unsigned lane = threadIdx.x & 31u, wid = threadIdx.x >> 5;
#pragma unroll
    for (int o = 16; o > 0; o >>= 1) v += __shfl_down_sync(0xffffffffu, v, o);
    if (lane == 0) redd[wid] = v;
    __syncthreads();
    int nw = (blockDim.x + 31) >> 5;
    v = (threadIdx.x < (unsigned)nw) ? redd[threadIdx.x] : 0.0;
    if (wid == 0) {
#pragma unroll
        for (int o = 16; o > 0; o >>= 1) v += __shfl_down_sync(0xffffffffu, v, o);
    }
    return v;
}

// fast exp2 for y in [-30, 16]; FMA-only (no MUFU). rel err ~1e-7.
__device__ __forceinline__ float fexp2(float y) {
    float fk = y + 12582912.0f;
    int   k  = __float_as_int(fk) - 0x4B400000;
    float r  = y - (fk - 12582912.0f);
    float p  = 1.5403530e-4f;
    p = fmaf(p, r, 1.3333558e-3f);
    p = fmaf(p, r, 9.6181291e-3f);
    p = fmaf(p, r, 5.5504109e-2f);
    p = fmaf(p, r, 2.4022651e-1f);
    p = fmaf(p, r, 6.9314718e-1f);
    p = fmaf(p, r, 1.0f);
    return p * __int_as_float((k + 127) << 23);
}

// ---------------- mma / ldmatrix / cp.async helpers (sm_80+ PTX) ----------------
__device__ __forceinline__ void mma_f16(float* d, const uint32_t* a, const uint32_t* b) {
    asm volatile(
        "mma.sync.aligned.m16n8k16.row.col.f32.f16.f16.f32 "
        "{%0,%1,%2,%3}, {%4,%5,%6,%7}, {%8,%9}, {%0,%1,%2,%3};"
        : "+f"(d[0]), "+f"(d[1]), "+f"(d[2]), "+f"(d[3])
        : "r"(a[0]), "r"(a[1]), "r"(a[2]), "r"(a[3]), "r"(b[0]), "r"(b[1]));
}
__device__ __forceinline__ void ldsm_x4(uint32_t* r, uint32_t addr) {
    asm volatile("ldmatrix.sync.aligned.m8n8.x4.shared.b16 {%0,%1,%2,%3}, [%4];"
                 : "=r"(r[0]), "=r"(r[1]), "=r"(r[2]), "=r"(r[3]) : "r"(addr));
}
__device__ __forceinline__ void ldsm_x2(uint32_t* r, uint32_t addr) {
    asm volatile("ldmatrix.sync.aligned.m8n8.x2.shared.b16 {%0,%1}, [%2];"
                 : "=r"(r[0]), "=r"(r[1]) : "r"(addr));
}
__device__ __forceinline__ uint32_t smem_u32(const void* p) {
    uint32_t a;
    asm("{ .reg .u64 t; cvta.to.shared.u64 t, %1; cvt.u32.u64 %0, t; }" : "=r"(a) : "l"(p));
    return a;
}
#define CP_ASYNC16(dst, src) \
    asm volatile("cp.async.cg.shared.global [%0], [%1], 16;" :: "r"(dst), "l"(src) : "memory")
#define CP_COMMIT() asm volatile("cp.async.commit_group;" ::: "memory")
#define CP_WAIT0()  asm volatile("cp.async.wait_group 0;" ::: "memory")

// fp16 C decode: 4 cols from a uint2
__device__ __forceinline__ void dec_c4(uint2 cu, float* c) {
    float2 a = __half22float2(*reinterpret_cast<__half2*>(&cu.x));
    float2 b = __half22float2(*reinterpret_cast<__half2*>(&cu.y));
    c[0] = a.x; c[1] = a.y; c[2] = b.x; c[3] = b.y;
}
// 8 halves from uint4
__device__ __forceinline__ void dec8(uint4 pv, float* f) {
    float2 a = __half22float2(*reinterpret_cast<__half2*>(&pv.x));
    float2 b = __half22float2(*reinterpret_cast<__half2*>(&pv.y));
    float2 c = __half22float2(*reinterpret_cast<__half2*>(&pv.z));
    float2 d = __half22float2(*reinterpret_cast<__half2*>(&pv.w));
    f[0] = a.x; f[1] = a.y; f[2] = b.x; f[3] = b.y;
    f[4] = c.x; f[5] = c.y; f[6] = d.x; f[7] = d.y;
}

// ---------------- small kernels ----------------
// init + Y-norms
__global__ void k_init(const float* __restrict__ YP, const float* __restrict__ YQ) {
    int t = blockIdx.x * blockDim.x + threadIdx.x;
    if (t == 0) { g_max_cx = 0u; g_max_cy = 0u; g_max_c = 0u; }
    if (t < NN) {
        g_w[t] = 1.0f;
        float sp = 0.f, sq = 0.f;
#pragma unroll
        for (int c = 0; c < NCLS; c++) {
            float tp = YP[(size_t)t * NCLS + c];
            float tq = YQ[(size_t)t * NCLS + c];
            sp += tp * tp; sq += tq * tq;
        }
        g_yp2[t] = sp; g_yq2[t] = sq;
    }
}

__global__ void k_norm512(const float* __restrict__ XP, const float* __restrict__ XQ) {
    int i = blockIdx.x;
    const float* X = blockIdx.y ? XQ : XP;
    float4 v = reinterpret_cast<const float4*>(X)[(size_t)i * (DD / 4) + threadIdx.x];
    float s = v.x * v.x + v.y * v.y + v.z * v.z + v.w * v.w;
    s = blockReduceSum(s);
    if (threadIdx.x == 0) (blockIdx.y ? g_xq2 : g_xp2)[i] = s;
}

// convert X to fp16 planes (rn)
__global__ void __launch_bounds__(256) k_split(const float* __restrict__ XP, const float* __restrict__ XQ) {
    const float4* src = reinterpret_cast<const float4*>(blockIdx.y ? XQ : XP);
    __half* Hh = blockIdx.y ? g_Bh : g_Ah;
    int n4 = NN * DD / 4;
    for (int i = blockIdx.x * 256 + threadIdx.x; i < n4; i += gridDim.x * 256) {
        float4 v = src[i];
        union { __half2 h[2]; uint2 u; } ph;
        ph.h[0] = __floats2half2_rn(v.x, v.y);
        ph.h[1] = __floats2half2_rn(v.z, v.w);
        reinterpret_cast<uint2*>(Hh)[i] = ph.u;
    }
}

// ---------------- single-pass FP16 mma.sync GEMM (ldmatrix fragments) ----------
#define ROWW 20                           // words per row (32 halves + pad)
#define PLANE_B (128 * ROWW * 4)          // bytes per plane: 10240
#define BUF_B (2 * PLANE_B)               // planes Ah, Bh: 20480
#define SMEM_GEMM (2 * BUF_B)             // 40960

__global__ void __launch_bounds__(256, 2)
k_gemm_mma(const float* __restrict__ YPg, const float* __restrict__ YQg) {
    extern __shared__ float sm[];
    const int tid = threadIdx.x;
    const int wid = tid >> 5, lane = tid & 31;
    const int warp_m = wid >> 2, warp_n = wid & 3;
    const int g = lane >> 2, t4 = lane & 3;
    const int row0 = blockIdx.y * 128;
    const int col0 = blockIdx.x * 128;

    const uint32_t smb = smem_u32(sm);

    // ldmatrix source addresses (per-lane), kk=0, buf=0:
    // A x4: lane L -> row (L&7) + ((L>>3)&1)*8, k-half-block ((L>>4)&1) (+16B)
    // B x2: lane L -> row (L&7), k-half-block ((L>>3)&1) (+16B)
    uint32_t a_base[4], b_base[4];
    {
        const int ar = (lane & 7) + ((lane >> 3) & 1) * 8;
        const uint32_t ak = ((lane >> 4) & 1) * 16;
        const int br = lane & 7;
        const uint32_t bk = ((lane >> 3) & 1) * 16;
#pragma unroll
        for (int mt = 0; mt < 4; mt++)
            a_base[mt] = smb + (uint32_t)((warp_m * 64 + mt * 16 + ar) * 80) + ak;
#pragma unroll
        for (int nt = 0; nt < 4; nt++)
            b_base[nt] = smb + PLANE_B + (uint32_t)((warp_n * 32 + nt * 8 + br) * 80) + bk;
    }

    float acc[4][4][4];
#pragma unroll
    for (int mt = 0; mt < 4; mt++)
#pragma unroll
        for (int nt = 0; nt < 4; nt++)
#pragma unroll
            for (int q = 0; q < 4; q++) acc[mt][nt][q] = 0.f;

    auto issue = [&](int ch, int buf) {
        const uint32_t base = smb + (uint32_t)buf * BUF_B;
#pragma unroll
        for (int q = 0; q < 4; q++) {
            int idx = tid + q * 256;          // 0..1023
            int plane = idx >> 9;             // 0=Ah,1=Bh
            int r = (idx >> 2) & 127;
            int c16 = idx & 3;
            uint32_t dst = base + (uint32_t)plane * PLANE_B + (uint32_t)(r * 80 + c16 * 16);
            const __half* gp = plane ? g_Bh : g_Ah;
            int rg = (plane ? col0 : row0) + r;
            const __half* src = gp + (size_t)rg * DD + ch * 32 + c16 * 8;
            CP_ASYNC16(dst, src);
        }
        CP_COMMIT();
    };

    issue(0, 0);
    for (int ch = 0; ch < 16; ch++) {
        const int buf = ch & 1;
        CP_WAIT0();
        __syncthreads();
        if (ch < 15) issue(ch + 1, buf ^ 1);
        const uint32_t bufo = (uint32_t)buf * BUF_B;
#pragma unroll
        for (int kk = 0; kk < 2; kk++) {
            const uint32_t koff = bufo + (uint32_t)kk * 32;   // kk*8 words = 32 bytes
            uint32_t ah[4][4];
#pragma unroll
            for (int mt = 0; mt < 4; mt++) ldsm_x4(ah[mt], a_base[mt] + koff);
            uint32_t bh[4][2];
#pragma unroll
            for (int nt = 0; nt < 4; nt++) ldsm_x2(bh[nt], b_base[nt] + koff);
#pragma unroll
            for (int mt = 0; mt < 4; mt++)
#pragma unroll
                for (int nt = 0; nt < 4; nt++)
                    mma_f16(acc[mt][nt], ah[mt], bh[nt]);
        }
        __syncthreads();
    }

    // ---- epilogue staging (reuse smem) ----
    if (tid < 128) {
        sm[tid]        = g_xq2[col0 + tid];
        sm[128 + tid]  = g_yq2[col0 + tid];
        sm[2816 + tid] = g_yp2[row0 + tid];
    }
    for (int i = tid; i < 128 * NCLS; i += 256) {
        sm[256 + i]  = YQg[(size_t)col0 * NCLS + i];
        sm[1536 + i] = YPg[(size_t)row0 * NCLS + i];
    }
    __syncthreads();

    float maxcx = 0.f;
#pragma unroll
    for (int mt = 0; mt < 4; mt++) {
        const int r1 = warp_m * 64 + mt * 16 + g;
        const int r2 = r1 + 8;
        const float xp2a = g_xp2[row0 + r1];
        const float xp2b = g_xp2[row0 + r2];
#pragma unroll
        for (int nt = 0; nt < 4; nt++) {
            const int n0 = warp_n * 32 + nt * 8 + 2 * t4;
            const float xq0 = sm[n0], xq1 = sm[n0 + 1];
            float c00 = fmaxf(xp2a + xq0 - 2.f * acc[mt][nt][0], 0.f);
            float c01 = fmaxf(xp2a + xq1 - 2.f * acc[mt][nt][1], 0.f);
            float c10 = fmaxf(xp2b + xq0 - 2.f * acc[mt][nt][2], 0.f);
            float c11 = fmaxf(xp2b + xq1 - 2.f * acc[mt][nt][3], 0.f);
            __half2 h0 = __floats2half2_rn(c00, c01);
            __half2 h1 = __floats2half2_rn(c10, c11);
            *reinterpret_cast<__half2*>(&g_Ch[(size_t)(row0 + r1) * NN + col0 + n0]) = h0;
            *reinterpret_cast<__half2*>(&g_Ch[(size_t)(row0 + r2) * NN + col0 + n0]) = h1;
            float2 q0 = __half22float2(h0);
            float2 q1 = __half22float2(h1);
            maxcx = fmaxf(maxcx, fmaxf(fmaxf(q0.x, q0.y), fmaxf(q1.x, q1.y)));
        }
    }
#pragma unroll
    for (int o = 16; o > 0; o >>= 1) maxcx = fmaxf(maxcx, __shfl_xor_sync(0xffffffffu, maxcx, o));
    if (lane == 0) atomicMax(&g_max_cx, __float_as_uint(maxcx));

    {
        const int r = tid & 127;
        const int j0 = (tid >> 7) * 64;
        float ypv[NCLS];
#pragma unroll
        for (int d = 0; d < NCLS; d++) ypv[d] = sm[1536 + r * NCLS + d];
        const float yp2r = sm[2816 + r];
        float mx = 0.f;
        for (int j = j0; j < j0 + 64; j++) {
            float dot = 0.f;
#pragma unroll
            for (int d = 0; d < NCLS; d++) dot = fmaf(ypv[d], sm[256 + j * NCLS + d], dot);
            float cy = fmaxf(yp2r + sm[128 + j] - 2.f * dot, 0.f);
            mx = fmaxf(mx, cy);
        }
#pragma unroll
        for (int o = 16; o > 0; o >>= 1) mx = fmaxf(mx, __shfl_xor_sync(0xffffffffu, mx, o));
        if (lane == 0) atomicMax(&g_max_cy, __float_as_uint(mx));
    }
}

// ---------------- max(C) over all elements (C = CX + lw*CY on the fly) ----------------
__global__ void __launch_bounds__(256) k_maxc(const float* __restrict__ YP, const float* __restrict__ YQ) {
    __shared__ float YPs[16][NCLS];
    __shared__ float yp2s[16];
    const int i0 = blockIdx.x * 16;
    const int tid = threadIdx.x;
    if (tid < 16 * NCLS) { int r = tid / NCLS, c = tid - r * NCLS; YPs[r][c] = YP[(size_t)(i0 + r) * NCLS + c]; }
    if (tid < 16) yp2s[tid] = g_yp2[i0 + tid];
    __syncthreads();
    float cxm = __uint_as_float(g_max_cx);
    float cym = __uint_as_float(g_max_cy);
    float lw = (cym == 0.f) ? 0.f : cxm / cym;
    float localmax = 0.f;
    for (int j0 = tid * 4; j0 < NN; j0 += 1024) {
        float yq[4][NCLS], yq2[4];
#pragma unroll
        for (int c = 0; c < 4; c++) {
#pragma unroll
            for (int d = 0; d < NCLS; d += 2) {
                float2 t = __ldg(reinterpret_cast<const float2*>(&YQ[(size_t)(j0 + c) * NCLS + d]));
                yq[c][d] = t.x; yq[c][d + 1] = t.y;
            }
            yq2[c] = g_yq2[j0 + c];
        }
#pragma unroll
        for (int r = 0; r < 16; r++) {
            uint2 cu = *reinterpret_cast<const uint2*>(&g_Ch[(size_t)(i0 + r) * NN + j0]);
            float cxa[4]; dec_c4(cu, cxa);
#pragma unroll
            for (int c = 0; c < 4; c++) {
                float dot = 0.f;
#pragma unroll
                for (int d = 0; d < NCLS; d++) dot = fmaf(YPs[r][d], yq[c][d], dot);
                float cy = fmaxf(yp2s[r] + yq2[c] - 2.f * dot, 0.f);
                localmax = fmaxf(localmax, cxa[c] + lw * cy);
            }
        }
    }
#pragma unroll
    for (int o = 16; o > 0; o >>= 1)
        localmax = fmaxf(localmax, __shfl_xor_sync(0xffffffffu, localmax, o));
    if ((tid & 31) == 0) atomicMax(&g_max_c, __float_as_uint(localmax));
}

// ---------------- P' = 2^SHIFT * exp(-C/(reg*cmax)) as fp16 ----------------
__global__ void __launch_bounds__(256) k_exp(const float* __restrict__ YP, const float* __restrict__ YQ) {
    __shared__ float YPs[16][NCLS];
    __shared__ float yp2s[16];
    const int i0 = blockIdx.x * 16;
    const int tid = threadIdx.x;
    if (tid < 16 * NCLS) { int r = tid / NCLS, c = tid - r * NCLS; YPs[r][c] = YP[(size_t)(i0 + r) * NCLS + c]; }
    if (tid < 16) yp2s[tid] = g_yp2[i0 + tid];
    __syncthreads();
    float cxm = __uint_as_float(g_max_cx);
    float cym = __uint_as_float(g_max_cy);
    float lw = (cym == 0.f) ? 0.f : cxm / cym;
    float cmax = __uint_as_float(g_max_c);
    float sc = 1.4426950408889634f / (REG_E * cmax);
    for (int j0 = tid * 4; j0 < NN; j0 += 1024) {
        float yq[4][NCLS], yq2[4];
#pragma unroll
        for (int c = 0; c < 4; c++) {
#pragma unroll
            for (int d = 0; d < NCLS; d += 2) {
                float2 t = __ldg(reinterpret_cast<const float2*>(&YQ[(size_t)(j0 + c) * NCLS + d]));
                yq[c][d] = t.x; yq[c][d + 1] = t.y;
            }
            yq2[c] = g_yq2[j0 + c];
        }
#pragma unroll
        for (int r = 0; r < 16; r++) {
            uint2 cu = *reinterpret_cast<const uint2*>(&g_Ch[(size_t)(i0 + r) * NN + j0]);
            float cxa[4]; dec_c4(cu, cxa);
            float pv[4];
#pragma unroll
            for (int c = 0; c < 4; c++) {
                float dot = 0.f;
#pragma unroll
                for (int d = 0; d < NCLS; d++) dot = fmaf(YPs[r][d], yq[c][d], dot);
                float cy = fmaxf(yp2s[r] + yq2[c] - 2.f * dot, 0.f);
                float v = cxa[c] + lw * cy;
                pv[c] = fexp2(fmaf(-v, sc, SHIFT));
            }
            union { __half2 h[2]; uint2 u; } pk;
            pk.h[0] = __floats2half2_rn(pv[0], pv[1]);
            pk.h[1] = __floats2half2_rn(pv[2], pv[3]);
            *reinterpret_cast<uint2*>(&g_Ph[(size_t)(i0 + r) * NN + j0]) = pk.u;
        }
    }
}

// ---------------- fused Sinkhorn iteration: one DRAM pass over fp16 P ----------------
#define IT_ROWS 32
#define STRIP 2
#define NSTRIP 16
#define STRIP_U4 (STRIP * (NN / 8))       // 2048 uint4
#define STRIP_B (STRIP_U4 * 16)           // 32768 bytes
#define SMEM_IT (2 * STRIP_B + 512)       // 66048

__global__ void __launch_bounds__(512, 2) k_iter() {
    extern __shared__ char smc[];
    uint4* bufs = reinterpret_cast<uint4*>(smc);
    float* zsm = reinterpret_cast<float*>(smc + 2 * STRIP_B);   // [2]
    float* red = zsm + 4;                                        // [32]
    const int tid = threadIdx.x;
    const int wid = tid >> 5, lane = tid & 31;
    const int r0 = blockIdx.x * IT_ROWS;
    const uint32_t smb = smem_u32(smc);

    float wreg[2][8];
#pragma unroll
    for (int k = 0; k < 2; k++) {
        const float* wp = &g_w[(k * 512 + tid) * 8];
        float4 a = *reinterpret_cast<const float4*>(wp);
        float4 b = *reinterpret_cast<const float4*>(wp + 4);
        wreg[k][0] = a.x; wreg[k][1] = a.y; wreg[k][2] = a.z; wreg[k][3] = a.w;
        wreg[k][4] = b.x; wreg[k][5] = b.y; wreg[k][6] = b.z; wreg[k][7] = b.w;
    }
    float colacc[2][8];
#pragma unroll
    for (int k = 0; k < 2; k++)
#pragma unroll
        for (int i = 0; i < 8; i++) colacc[k][i] = 0.f;

    auto issue = [&](int s, int b) {
        const __half* base = g_Ph + (size_t)(r0 + s * STRIP) * NN;
#pragma unroll
        for (int q = 0; q < 4; q++) {
            int idx = tid + q * 512;                // 0..2047
            int rr = idx >> 10, c8 = idx & 1023;
            uint32_t dst = smb + (uint32_t)b * STRIP_B + (uint32_t)idx * 16;
            const __half* src = base + (size_t)rr * NN + c8 * 8;
            CP_ASYNC16(dst, src);
        }
        CP_COMMIT();
    };

    issue(0, 0);
    for (int s = 0; s < NSTRIP; s++) {
        const int b = s & 1;
        CP_WAIT0();
        __syncthreads();
        if (s < NSTRIP - 1) issue(s + 1, b ^ 1);
        const uint4* st = bufs + b * STRIP_U4;

        // pass 1: row sums
        float rp[STRIP] = {0.f, 0.f};
#pragma unroll
        for (int r = 0; r < STRIP; r++)
#pragma unroll
            for (int k = 0; k < 2; k++) {
                uint4 pv = st[r * 1024 + k * 512 + tid];
                float f[8]; dec8(pv, f);
                float s0 = fmaf(f[0], wreg[k][0], f[1] * wreg[k][1]);
                s0 = fmaf(f[2], wreg[k][2], s0); s0 = fmaf(f[3], wreg[k][3], s0);
                float s1 = fmaf(f[4], wreg[k][4], f[5] * wreg[k][5]);
                s1 = fmaf(f[6], wreg[k][6], s1); s1 = fmaf(f[7], wreg[k][7], s1);
                rp[r] += s0 + s1;
            }
#pragma unroll
        for (int r = 0; r < STRIP; r++) {
            float v = rp[r];
#pragma unroll
            for (int o = 16; o > 0; o >>= 1) v += __shfl_down_sync(0xffffffffu, v, o);
            if (lane == 0) red[r * 16 + wid] = v;
        }
        __syncthreads();
        if (tid < STRIP) {
            float sum = 0.f;
#pragma unroll
            for (int w2 = 0; w2 < 16; w2++) sum += red[tid * 16 + w2];
            float z = (1.0f / NN) / sum;
            zsm[tid] = z;
            g_z[r0 + s * STRIP + tid] = z;
        }
        __syncthreads();

        // pass 2: column partials
#pragma unroll
        for (int r = 0; r < STRIP; r++) {
            float zz = zsm[r];
#pragma unroll
            for (int k = 0; k < 2; k++) {
                uint4 pv = st[r * 1024 + k * 512 + tid];
                float f[8]; dec8(pv, f);
#pragma unroll
                for (int i = 0; i < 8; i++) colacc[k][i] = fmaf(f[i], zz, colacc[k][i]);
            }
        }
    }

#pragma unroll
    for (int k = 0; k < 2; k++) {
        float* dst = &g_part[(size_t)blockIdx.x * NN + (size_t)(k * 512 + tid) * 8];
        *reinterpret_cast<float4*>(dst)     = make_float4(colacc[k][0], colacc[k][1], colacc[k][2], colacc[k][3]);
        *reinterpret_cast<float4*>(dst + 4) = make_float4(colacc[k][4], colacc[k][5], colacc[k][6], colacc[k][7]);
    }
}

// w = (1/M) / colsum over 256 block partials -- parallel + deterministic.
__global__ void __launch_bounds__(256) k_colred() {
    __shared__ float red2[8][32];
    const int tid = threadIdx.x;
    const int g = tid >> 5, jl = tid & 31;
    const int j = blockIdx.x * 32 + jl;
    float s = 0.f;
#pragma unroll 8
    for (int ch = g * 32; ch < g * 32 + 32; ch++)
        s += g_part[(size_t)ch * NN + j];
    red2[g][jl] = s;
    __syncthreads();
    if (tid < 32) {
        float t = 0.f;
#pragma unroll
        for (int q = 0; q < 8; q++) t += red2[q][tid];
        g_w[blockIdx.x * 32 + tid] = (1.0f / NN) / t;
    }
}

// ---------------- final objective ----------------
__global__ void __launch_bounds__(256) k_final(const float* __restrict__ YP, const float* __restrict__ YQ) {
    __shared__ float YPs[16][NCLS];
    __shared__ float yp2s[16];
    __shared__ float zs[16];
    const int i0 = blockIdx.x * 16;
    const int tid = threadIdx.x;
    if (tid < 16 * NCLS) { int r = tid / NCLS, c = tid - r * NCLS; YPs[r][c] = YP[(size_t)(i0 + r) * NCLS + c]; }
    if (tid < 16) { yp2s[tid] = g_yp2[i0 + tid]; zs[tid] = g_z[i0 + tid] * SHIFT_MUL; }
    __syncthreads();
    float cxm = __uint_as_float(g_max_cx);
    float cym = __uint_as_float(g_max_cy);
    float lw = (cym == 0.f) ? 0.f : cxm / cym;
    float cmax = __uint_as_float(g_max_c);
    float sc = 1.4426950408889634f / (REG_E * cmax);
    float acc = 0.f;
    for (int j0 = tid * 4; j0 < NN; j0 += 1024) {
        float yq[4][NCLS], yq2[4];
#pragma unroll
        for (int c = 0; c < 4; c++) {
#pragma unroll
            for (int d = 0; d < NCLS; d += 2) {
                float2 t = __ldg(reinterpret_cast<const float2*>(&YQ[(size_t)(j0 + c) * NCLS + d]));
                yq[c][d] = t.x; yq[c][d + 1] = t.y;
            }
            yq2[c] = g_yq2[j0 + c];
        }
        float4 wv = *reinterpret_cast<const float4*>(&g_w[j0]);
        float wa[4] = {wv.x, wv.y, wv.z, wv.w};
#pragma unroll
        for (int r = 0; r < 16; r++) {
            uint2 cu = *reinterpret_cast<const uint2*>(&g_Ch[(size_t)(i0 + r) * NN + j0]);
            float cxa[4]; dec_c4(cu, cxa);
            float zi = zs[r];
#pragma unroll
            for (int c = 0; c < 4; c++) {
                float dot = 0.f;
#pragma unroll
                for (int d = 0; d < NCLS; d++) dot = fmaf(YPs[r][d], yq[c][d], dot);
                float cy = fmaxf(yp2s[r] + yq2[c] - 2.f * dot, 0.f);
                float v = cxa[c] + lw * cy;
                float p = fexp2(-v * sc);
                acc = fmaf(v * p, zi * wa[c], acc);
            }
        }
    }
    acc = blockReduceSum(acc);
    if (tid == 0) g_bpart[blockIdx.x] = acc;
}

__global__ void __launch_bounds__(256) k_finalred(float* out) {
    double s = 0.0;
    for (int t = threadIdx.x; t < 512; t += 256) s += (double)g_bpart[t];
    s = blockReduceSumD(s);
    if (threadIdx.x == 0) out[0] = (float)s;
}

// ---------------- launch ----------------
extern "C" void kernel_launch(void* const* d_in, const int* in_sizes, int n_in,
                              void* d_out, int out_size) {
    const float* XQ = (const float*)d_in[0];   // (8192, 512)
    const float* YQ = (const float*)d_in[1];   // (8192, 10)
    const float* XP = (const float*)d_in[2];   // (8192, 512)
    const float* YP = (const float*)d_in[3];   // (8192, 10)
    float* out = (float*)d_out;

    cudaFuncSetAttribute(k_gemm_mma, cudaFuncAttributeMaxDynamicSharedMemorySize, SMEM_GEMM);
    cudaFuncSetAttribute(k_iter, cudaFuncAttributeMaxDynamicSharedMemorySize, SMEM_IT);

    k_init<<<32, 256>>>(YP, YQ);
    k_norm512<<<dim3(NN, 2), 128>>>(XP, XQ);
    k_split<<<dim3(512, 2), 256>>>(XP, XQ);

    k_gemm_mma<<<dim3(64, 64), 256, SMEM_GEMM>>>(YP, YQ);   // launch #4: ncu target
    k_maxc<<<NN / 16, 256>>>(YP, YQ);
    k_exp<<<NN / 16, 256>>>(YP, YQ);

    for (int it = 0; it < NIT; it++) {
        k_iter<<<256, 512, SMEM_IT>>>();
        k_colred<<<256, 256>>>();
    }

    k_final<<<NN / 16, 256>>>(YP, YQ);
    k_finalred<<<1, 256>>>(out);
}